// round 8
// baseline (speedup 1.0000x reference)
#include <cuda_runtime.h>
#include <cstdint>
#include <math.h>

// Problem constants (shapes are fixed by the dataset)
#define BB 8
#define CC 64
#define NN 8192
#define MM 2048
#define KNNK 16
#define FPS_M 1433   // int(2048 * 0.7)
#define RAND_M 615   // 2048 - 1433

#define FPS_T 256            // active threads in FPS blocks (8 warps)
#define FPS_PPT (NN / FPS_T) // 32 points per thread = 16 f32x2 pairs

// ---------------------------------------------------------------------------
// Threefry-2x32 core (jax threefry2x32 primitive)
// ---------------------------------------------------------------------------
__host__ __device__ __forceinline__ void threefry2x32(
    uint32_t k0, uint32_t k1, uint32_t c0, uint32_t c1,
    uint32_t* o0, uint32_t* o1) {
  uint32_t ks2 = 0x1BD11BDAu ^ k0 ^ k1;
  uint32_t x0 = c0 + k0;
  uint32_t x1 = c1 + k1;
#define TF_ROTL(v, r) (((v) << (r)) | ((v) >> (32 - (r))))
#define TF_ROUND(r) do { x0 += x1; x1 = TF_ROTL(x1, r); x1 ^= x0; } while (0)
  TF_ROUND(13); TF_ROUND(15); TF_ROUND(26); TF_ROUND(6);
  x0 += k1; x1 += ks2 + 1u;
  TF_ROUND(17); TF_ROUND(29); TF_ROUND(16); TF_ROUND(24);
  x0 += ks2; x1 += k0 + 2u;
  TF_ROUND(13); TF_ROUND(15); TF_ROUND(26); TF_ROUND(6);
  x0 += k0; x1 += k1 + 3u;
  TF_ROUND(17); TF_ROUND(29); TF_ROUND(16); TF_ROUND(24);
  x0 += k1; x1 += ks2 + 4u;
  TF_ROUND(13); TF_ROUND(15); TF_ROUND(26); TF_ROUND(6);
  x0 += ks2; x1 += k0 + 5u;
#undef TF_ROUND
#undef TF_ROTL
  *o0 = x0; *o1 = x1;
}

struct FpsArgs  { int start[BB]; };
struct PermArgs { uint32_t sub[BB][2][2]; };

__device__ int g_idx[BB * MM];

// ---------------------------------------------------------------------------
// Packed f32x2 helpers (bit-exact per-lane .rn semantics, sm_103a)
// ---------------------------------------------------------------------------
__device__ __forceinline__ unsigned long long f2_pack(float lo, float hi) {
  unsigned long long o;
  asm("mov.b64 %0, {%1, %2};" : "=l"(o) : "f"(lo), "f"(hi));
  return o;
}
__device__ __forceinline__ void f2_unpack(unsigned long long v, float* lo, float* hi) {
  asm("mov.b64 {%0, %1}, %2;" : "=f"(*lo), "=f"(*hi) : "l"(v));
}
__device__ __forceinline__ unsigned long long f2_add(unsigned long long a,
                                                     unsigned long long b) {
  unsigned long long o;
  asm("add.rn.f32x2 %0, %1, %2;" : "=l"(o) : "l"(a), "l"(b));
  return o;
}
__device__ __forceinline__ unsigned long long f2_mul(unsigned long long a,
                                                     unsigned long long b) {
  unsigned long long o;
  asm("mul.rn.f32x2 %0, %1, %2;" : "=l"(o) : "l"(a), "l"(b));
  return o;
}

// monotone map: float bits -> u32 preserving float ordering (handles negatives)
__device__ __forceinline__ uint32_t f2ord(float f) {
  uint32_t u = __float_as_uint(f);
  return u ^ ((u & 0x80000000u) ? 0xFFFFFFFFu : 0x80000000u);
}

// ---------------------------------------------------------------------------
// Host-side PRNG derivation — PARTITIONABLE threefry semantics
// ---------------------------------------------------------------------------
static void compute_consts(FpsArgs* fa, PermArgs* pa) {
  for (int b = 0; b < BB; b++) {
    uint32_t fk0, fk1;
    threefry2x32(0u, 42u, 0u, (uint32_t)b, &fk0, &fk1);
    uint32_t k20, k21;
    threefry2x32(fk0, fk1, 0u, 1u, &k20, &k21);
    uint32_t s0, s1;
    threefry2x32(k20, k21, 0u, 0u, &s0, &s1);
    fa->start[b] = (int)((s0 ^ s1) & (NN - 1));
  }
  uint32_t rk0, rk1;
  threefry2x32(0u, 42u, 0u, 1u, &rk0, &rk1);
  for (int b = 0; b < BB; b++) {
    uint32_t k0, k1;
    threefry2x32(rk0, rk1, 0u, (uint32_t)b, &k0, &k1);
    for (int r = 0; r < 2; r++) {
      uint32_t n0, n1, c0, c1;
      threefry2x32(k0, k1, 0u, 0u, &n0, &n1);
      threefry2x32(k0, k1, 0u, 1u, &c0, &c1);
      pa->sub[b][r][0] = c0;
      pa->sub[b][r][1] = c1;
      k0 = n0; k1 = n1;
    }
  }
}

// Fused FPS + permutation kernel. Blocks 0..7 = FPS(batch), 8..15 = perm(batch)
#define SMEM_FUSED (3 * NN * 4 + 4 * 32 * 4 + 64)

__global__ __launch_bounds__(1024, 1)
void fused_kernel(const float* __restrict__ pos, FpsArgs fargs, PermArgs pargs) {
  extern __shared__ char smem_raw[];
  const int tid = threadIdx.x;

  if (blockIdx.x < BB) {
    // ===================== FPS: 8 warps only =====================
    if (tid >= FPS_T) return;  // 24 whole warps exit before any barrier
    const int b = blockIdx.x;
    float* sax = (float*)smem_raw;
    float* say = sax + NN;
    float* saz = say + NN;
    uint32_t* swval = (uint32_t*)(saz + NN);   // [2][8] (padded)
    uint32_t* swidx = swval + 64;              // [2][8] (padded)

    const float* px = pos + (size_t)b * 3 * NN;
    const float* py = px + NN;
    const float* pz = px + 2 * NN;

    // 32 points/thread as 16 f32x2 pairs: pair j = (2j*256+tid, (2j+1)*256+tid)
    unsigned long long rx2[16], ry2[16], rz2[16];
    float rd[32];
#pragma unroll
    for (int j = 0; j < 16; j++) {
      int i0 = (2 * j) * FPS_T + tid;
      int i1 = i0 + FPS_T;
      float x0 = px[i0], x1 = px[i1];
      float y0 = py[i0], y1 = py[i1];
      float z0 = pz[i0], z1 = pz[i1];
      rx2[j] = f2_pack(x0, x1);
      ry2[j] = f2_pack(y0, y1);
      rz2[j] = f2_pack(z0, z1);
      sax[i0] = x0; sax[i1] = x1;
      say[i0] = y0; say[i1] = y1;
      saz[i0] = z0; saz[i1] = z1;
      rd[2 * j] = 1e10f; rd[2 * j + 1] = 1e10f;
    }
    __syncthreads();

    const int start = fargs.start[b];
    if (tid == 0) g_idx[b * MM] = start;
    float bx = sax[start], by = say[start], bz = saz[start];

    const int lane = tid & 31, warp = tid >> 5;
    int par = 0;

    for (int it = 1; it < FPS_M; ++it) {
      unsigned long long nbx2 = f2_pack(-bx, -bx);
      unsigned long long nby2 = f2_pack(-by, -by);
      unsigned long long nbz2 = f2_pack(-bz, -bz);

      float bestv = -1.0f;
      int   besti = 0;
#pragma unroll
      for (int j = 0; j < 16; j++) {
        unsigned long long dx2 = f2_add(rx2[j], nbx2);
        unsigned long long dy2 = f2_add(ry2[j], nby2);
        unsigned long long dz2 = f2_add(rz2[j], nbz2);
        unsigned long long dd2 =
            f2_add(f2_add(f2_mul(dx2, dx2), f2_mul(dy2, dy2)), f2_mul(dz2, dz2));
        float d0, d1;
        f2_unpack(dd2, &d0, &d1);
        float nv0 = fminf(rd[2 * j], d0);
        rd[2 * j] = nv0;
        if (nv0 > bestv) { bestv = nv0; besti = (2 * j) * FPS_T + tid; }
        float nv1 = fminf(rd[2 * j + 1], d1);
        rd[2 * j + 1] = nv1;
        if (nv1 > bestv) { bestv = nv1; besti = (2 * j + 1) * FPS_T + tid; }
      }
      // warp argmax via redux: distances >= 0 -> float bits monotone in value
      uint32_t bits = __float_as_uint(bestv);
      uint32_t wmax = __reduce_max_sync(0xffffffffu, bits);
      uint32_t cand = (bits == wmax) ? (uint32_t)besti : 0xFFFFFFFFu;
      uint32_t wi   = __reduce_min_sync(0xffffffffu, cand);  // lowest tied idx
      if (lane == 0) { swval[par * 8 + warp] = wmax; swidx[par * 8 + warp] = wi; }
      __syncthreads();
      // all 8 warps reduce the 8 partials (cheap: 2 pred-LDS + 2 redux each)
      uint32_t v  = (lane < 8) ? swval[par * 8 + lane] : 0u;
      uint32_t bmax = __reduce_max_sync(0xffffffffu, v);
      uint32_t bc = (lane < 8 && v == bmax) ? swidx[par * 8 + lane] : 0xFFFFFFFFu;
      uint32_t w  = __reduce_min_sync(0xffffffffu, bc);
      if (tid == 0) g_idx[b * MM + it] = (int)w;
      bx = sax[w]; by = say[w]; bz = saz[w];
      par ^= 1;
    }
  } else {
    // ===================== random-permutation tail =====================
    const int b = blockIdx.x - BB;
    unsigned long long* A = (unsigned long long*)smem_raw;  // NN entries

    for (int r = 0; r < 2; ++r) {
      const uint32_t k0 = pargs.sub[b][r][0];
      const uint32_t k1 = pargs.sub[b][r][1];
      uint32_t keys[8];
#pragma unroll
      for (int t = 0; t < 8; ++t) {
        int i = tid + t * 1024;
        uint32_t y0, y1;
        threefry2x32(k0, k1, 0u, (uint32_t)i, &y0, &y1);
        keys[t] = y0 ^ y1;
      }
#pragma unroll
      for (int t = 0; t < 8; ++t) {
        int i = tid + t * 1024;
        uint32_t v = (r == 0) ? (uint32_t)i : (uint32_t)(A[i] & 0x1FFFull);
        A[i] = ((unsigned long long)keys[t] << 32) |
               ((unsigned long long)(uint32_t)i << 13) | v;
      }
      __syncthreads();
      for (int kk = 2; kk <= NN; kk <<= 1) {
        for (int jj = kk >> 1; jj > 0; jj >>= 1) {
#pragma unroll
          for (int t = 0; t < 8; ++t) {
            int i = tid + t * 1024;
            int ixj = i ^ jj;
            if (ixj > i) {
              bool up = ((i & kk) == 0);
              unsigned long long a = A[i], c = A[ixj];
              if ((a > c) == up) { A[i] = c; A[ixj] = a; }
            }
          }
          __syncthreads();
        }
      }
    }
    for (int t = tid; t < RAND_M; t += 1024)
      g_idx[b * MM + FPS_M + t] = (int)(A[t] & 0x1FFFull);
  }
}

// ---------------------------------------------------------------------------
// KNN + softmax aggregation: WARP-per-center (unchanged — proven fast)
// ---------------------------------------------------------------------------
__global__ __launch_bounds__(256, 2)
void knn_kernel(const float* __restrict__ x, const float* __restrict__ pos,
                float* __restrict__ out) {
  const int warp = threadIdx.x >> 5, lane = threadIdx.x & 31;
  const int b  = blockIdx.x >> 8;
  const int ci = ((blockIdx.x & 255) << 3) + warp;
  const float* px = pos + (size_t)b * 3 * NN;

  __shared__ float sax[2048], say[2048], saz[2048], ssn[2048];

  const int cidx = g_idx[b * MM + ci];
  const float sx = px[cidx], sy = px[NN + cidx], sz = px[2 * NN + cidx];
  const float sm = __fadd_rn(__fadd_rn(__fmul_rn(sx, sx), __fmul_rn(sy, sy)),
                             __fmul_rn(sz, sz));

  float kd[KNNK];
  int   ki[KNNK];
#pragma unroll
  for (int k = 0; k < KNNK; k++) { kd[k] = 3.4e38f; ki[k] = 0; }
  float worstv = 3.4e38f;
  int   worsti = 0, worsts = 0;

  for (int tile = 0; tile < 4; ++tile) {
    __syncthreads();
    const int base = tile * 2048;
    for (int t = threadIdx.x; t < 2048; t += 256) {
      float ax = px[base + t];
      float ay = px[NN + base + t];
      float az = px[2 * NN + base + t];
      sax[t] = ax; say[t] = ay; saz[t] = az;
      ssn[t] = __fadd_rn(__fadd_rn(__fmul_rn(ax, ax), __fmul_rn(ay, ay)),
                         __fmul_rn(az, az));
    }
    __syncthreads();
#pragma unroll 4
    for (int tt = 0; tt < 64; ++tt) {
      const int t = lane + tt * 32;
      float dot = __fadd_rn(
          __fadd_rn(__fmul_rn(sx, sax[t]), __fmul_rn(sy, say[t])),
          __fmul_rn(sz, saz[t]));
      float d2 = __fsub_rn(__fadd_rn(sm, ssn[t]), __fmul_rn(2.0f, dot));
      if (d2 < worstv) {
        const int gi = base + t;
#pragma unroll
        for (int k = 0; k < KNNK; k++)
          if (k == worsts) { kd[k] = d2; ki[k] = gi; }
        worstv = kd[0]; worsti = ki[0]; worsts = 0;
#pragma unroll
        for (int k = 1; k < KNNK; k++) {
          if (kd[k] > worstv || (kd[k] == worstv && ki[k] > worsti)) {
            worstv = kd[k]; worsti = ki[k]; worsts = k;
          }
        }
      }
    }
  }

  unsigned long long Kq[KNNK];
#pragma unroll
  for (int k = 0; k < KNNK; k++)
    Kq[k] = ((unsigned long long)f2ord(kd[k]) << 32) | (uint32_t)ki[k];

  unsigned long long top[KNNK];
#pragma unroll
  for (int r = 0; r < KNNK; ++r) {
    unsigned long long m = Kq[0];
#pragma unroll
    for (int k = 1; k < KNNK; k++) m = (Kq[k] < m) ? Kq[k] : m;
#pragma unroll
    for (int off = 16; off; off >>= 1) {
      unsigned long long o = __shfl_xor_sync(0xffffffffu, m, off);
      m = (o < m) ? o : m;
    }
    top[r] = m;
    bool own = false;
#pragma unroll
    for (int k = 0; k < KNNK; k++) {
      bool hit = (!own && Kq[k] == m);
      if (hit) { Kq[k] = 0xFFFFFFFFFFFFFFFFull; own = true; }
    }
  }

  int   id[KNNK];
  float w[KNNK];
  float maxl = -3.4e38f;
#pragma unroll
  for (int k = 0; k < KNNK; k++) {
    id[k] = (int)(top[k] & 0xFFFFFFFFull);
    float dx = px[id[k]] - sx, dy = px[NN + id[k]] - sy, dz = px[2 * NN + id[k]] - sz;
    float dn = sqrtf(dx * dx + dy * dy + dz * dz);
    dn = fmaxf(dn, 1e-6f);
    float l = -dn / 0.2f;
    w[k] = l;
    maxl = fmaxf(maxl, l);
  }
  float s = 0.0f;
#pragma unroll
  for (int k = 0; k < KNNK; k++) { w[k] = expf(w[k] - maxl); s += w[k]; }
  float inv = 1.0f / s;
#pragma unroll
  for (int k = 0; k < KNNK; k++) w[k] *= inv;

  if (lane == 0) {
    float* outpos = out + (size_t)BB * CC * MM;
    outpos[(size_t)b * 3 * MM + ci] = sx;
    outpos[(size_t)b * 3 * MM + MM + ci] = sy;
    outpos[(size_t)b * 3 * MM + 2 * MM + ci] = sz;
  }

  const float* xb = x + (size_t)b * CC * NN;
  const float* r0 = xb + (size_t)lane * NN;
  const float* r1 = xb + (size_t)(lane + 32) * NN;
  float acc0 = 0.0f, acc1 = 0.0f;
#pragma unroll
  for (int k = 0; k < KNNK; k++) {
    acc0 += w[k] * r0[id[k]];
    acc1 += w[k] * r1[id[k]];
  }
  out[((size_t)b * CC + lane) * MM + ci] = acc0;
  out[((size_t)b * CC + lane + 32) * MM + ci] = acc1;
}

// ---------------------------------------------------------------------------
extern "C" void kernel_launch(void* const* d_in, const int* in_sizes, int n_in,
                              void* d_out, int out_size) {
  const float* x   = (const float*)d_in[0];
  const float* pos = (const float*)d_in[1];
  (void)in_sizes; (void)n_in; (void)out_size;

  FpsArgs fa;
  PermArgs pa;
  compute_consts(&fa, &pa);

  cudaFuncSetAttribute(fused_kernel,
                       cudaFuncAttributeMaxDynamicSharedMemorySize, SMEM_FUSED);

  fused_kernel<<<2 * BB, 1024, SMEM_FUSED>>>(pos, fa, pa);
  knn_kernel<<<BB * 256, 256>>>(x, pos, (float*)d_out);
}

// round 9
// speedup vs baseline: 1.4442x; 1.4442x over previous
#include <cuda_runtime.h>
#include <cstdint>
#include <math.h>

// Problem constants (shapes are fixed by the dataset)
#define BB 8
#define CC 64
#define NN 8192
#define MM 2048
#define KNNK 16
#define FPS_M 1433   // int(2048 * 0.7)
#define RAND_M 615   // 2048 - 1433

// ---------------------------------------------------------------------------
// Threefry-2x32 core (jax threefry2x32 primitive)
// ---------------------------------------------------------------------------
__host__ __device__ __forceinline__ void threefry2x32(
    uint32_t k0, uint32_t k1, uint32_t c0, uint32_t c1,
    uint32_t* o0, uint32_t* o1) {
  uint32_t ks2 = 0x1BD11BDAu ^ k0 ^ k1;
  uint32_t x0 = c0 + k0;
  uint32_t x1 = c1 + k1;
#define TF_ROTL(v, r) (((v) << (r)) | ((v) >> (32 - (r))))
#define TF_ROUND(r) do { x0 += x1; x1 = TF_ROTL(x1, r); x1 ^= x0; } while (0)
  TF_ROUND(13); TF_ROUND(15); TF_ROUND(26); TF_ROUND(6);
  x0 += k1; x1 += ks2 + 1u;
  TF_ROUND(17); TF_ROUND(29); TF_ROUND(16); TF_ROUND(24);
  x0 += ks2; x1 += k0 + 2u;
  TF_ROUND(13); TF_ROUND(15); TF_ROUND(26); TF_ROUND(6);
  x0 += k0; x1 += k1 + 3u;
  TF_ROUND(17); TF_ROUND(29); TF_ROUND(16); TF_ROUND(24);
  x0 += k1; x1 += ks2 + 4u;
  TF_ROUND(13); TF_ROUND(15); TF_ROUND(26); TF_ROUND(6);
  x0 += ks2; x1 += k0 + 5u;
#undef TF_ROUND
#undef TF_ROTL
  *o0 = x0; *o1 = x1;
}

struct FpsArgs  { int start[BB]; };
struct PermArgs { uint32_t sub[BB][2][2]; };

__device__ int g_idx[BB * MM];

// ---------------------------------------------------------------------------
// Packed f32x2 helpers (bit-exact per-lane .rn semantics, sm_103a)
// ---------------------------------------------------------------------------
__device__ __forceinline__ unsigned long long f2_pack(float lo, float hi) {
  unsigned long long o;
  asm("mov.b64 %0, {%1, %2};" : "=l"(o) : "f"(lo), "f"(hi));
  return o;
}
__device__ __forceinline__ void f2_unpack(unsigned long long v, float* lo, float* hi) {
  asm("mov.b64 {%0, %1}, %2;" : "=f"(*lo), "=f"(*hi) : "l"(v));
}
__device__ __forceinline__ unsigned long long f2_add(unsigned long long a,
                                                     unsigned long long b) {
  unsigned long long o;
  asm("add.rn.f32x2 %0, %1, %2;" : "=l"(o) : "l"(a), "l"(b));
  return o;
}
__device__ __forceinline__ unsigned long long f2_mul(unsigned long long a,
                                                     unsigned long long b) {
  unsigned long long o;
  asm("mul.rn.f32x2 %0, %1, %2;" : "=l"(o) : "l"(a), "l"(b));
  return o;
}

// monotone map: float bits -> u32 preserving float ordering (handles negatives)
__device__ __forceinline__ uint32_t f2ord(float f) {
  uint32_t u = __float_as_uint(f);
  return u ^ ((u & 0x80000000u) ? 0xFFFFFFFFu : 0x80000000u);
}

// ---------------------------------------------------------------------------
// Host-side PRNG derivation — PARTITIONABLE threefry semantics
// ---------------------------------------------------------------------------
static void compute_consts(FpsArgs* fa, PermArgs* pa) {
  for (int b = 0; b < BB; b++) {
    uint32_t fk0, fk1;
    threefry2x32(0u, 42u, 0u, (uint32_t)b, &fk0, &fk1);
    uint32_t k20, k21;
    threefry2x32(fk0, fk1, 0u, 1u, &k20, &k21);
    uint32_t s0, s1;
    threefry2x32(k20, k21, 0u, 0u, &s0, &s1);
    fa->start[b] = (int)((s0 ^ s1) & (NN - 1));
  }
  uint32_t rk0, rk1;
  threefry2x32(0u, 42u, 0u, 1u, &rk0, &rk1);
  for (int b = 0; b < BB; b++) {
    uint32_t k0, k1;
    threefry2x32(rk0, rk1, 0u, (uint32_t)b, &k0, &k1);
    for (int r = 0; r < 2; r++) {
      uint32_t n0, n1, c0, c1;
      threefry2x32(k0, k1, 0u, 0u, &n0, &n1);
      threefry2x32(k0, k1, 0u, 1u, &c0, &c1);
      pa->sub[b][r][0] = c0;
      pa->sub[b][r][1] = c1;
      k0 = n0; k1 = n1;
    }
  }
}

// Fused FPS + permutation kernel. Blocks 0..7 = FPS(batch), 8..15 = perm(batch)
// FPS branch is the R5-measured-best structure: 1024 threads, 8 pts/thread,
// u64-shfl warp reduce, warp0-only final reduce, two barriers per iteration.
#define SMEM_FUSED (3 * NN * 4 + 32 * 8 + 64)

__global__ __launch_bounds__(1024, 1)
void fused_kernel(const float* __restrict__ pos, FpsArgs fargs, PermArgs pargs) {
  extern __shared__ char smem_raw[];
  const int tid = threadIdx.x;

  if (blockIdx.x < BB) {
    // ===================== FPS =====================
    const int b = blockIdx.x;
    float* sax = (float*)smem_raw;
    float* say = sax + NN;
    float* saz = say + NN;
    unsigned long long* swv = (unsigned long long*)(saz + NN);  // [32]
    int* s_w = (int*)(swv + 32);

    const float* px = pos + (size_t)b * 3 * NN;
    const float* py = px + NN;
    const float* pz = px + 2 * NN;

    unsigned long long rx2[4], ry2[4], rz2[4];
    float rd[8];
#pragma unroll
    for (int j = 0; j < 4; j++) {
      int i0 = (2 * j) * 1024 + tid;
      int i1 = i0 + 1024;
      float x0 = px[i0], x1 = px[i1];
      float y0 = py[i0], y1 = py[i1];
      float z0 = pz[i0], z1 = pz[i1];
      rx2[j] = f2_pack(x0, x1);
      ry2[j] = f2_pack(y0, y1);
      rz2[j] = f2_pack(z0, z1);
      sax[i0] = x0; sax[i1] = x1;
      say[i0] = y0; say[i1] = y1;
      saz[i0] = z0; saz[i1] = z1;
      rd[2 * j] = 1e10f; rd[2 * j + 1] = 1e10f;
    }
    __syncthreads();

    const int start = fargs.start[b];
    if (tid == 0) g_idx[b * MM] = start;
    float bx = sax[start], by = say[start], bz = saz[start];

    const int lane = tid & 31, warp = tid >> 5;

    for (int it = 1; it < FPS_M; ++it) {
      unsigned long long nbx2 = f2_pack(-bx, -bx);
      unsigned long long nby2 = f2_pack(-by, -by);
      unsigned long long nbz2 = f2_pack(-bz, -bz);

      float bestv = -1.0f;
      int   besti = 0;
#pragma unroll
      for (int j = 0; j < 4; j++) {
        unsigned long long dx2 = f2_add(rx2[j], nbx2);
        unsigned long long dy2 = f2_add(ry2[j], nby2);
        unsigned long long dz2 = f2_add(rz2[j], nbz2);
        unsigned long long dd2 =
            f2_add(f2_add(f2_mul(dx2, dx2), f2_mul(dy2, dy2)), f2_mul(dz2, dz2));
        float d0, d1;
        f2_unpack(dd2, &d0, &d1);
        float nv0 = fminf(rd[2 * j], d0);
        rd[2 * j] = nv0;
        if (nv0 > bestv) { bestv = nv0; besti = (2 * j) * 1024 + tid; }
        float nv1 = fminf(rd[2 * j + 1], d1);
        rd[2 * j + 1] = nv1;
        if (nv1 > bestv) { bestv = nv1; besti = (2 * j + 1) * 1024 + tid; }
      }
      // distances >= 0 so raw float bits are monotone; NN-idx -> lower idx wins
      unsigned long long key =
          ((unsigned long long)__float_as_uint(bestv) << 32) |
          (unsigned long long)(uint32_t)(NN - besti);
#pragma unroll
      for (int off = 16; off; off >>= 1) {
        unsigned long long o = __shfl_down_sync(0xffffffffu, key, off);
        key = (o > key) ? o : key;
      }
      if (lane == 0) swv[warp] = key;
      __syncthreads();
      if (warp == 0) {
        unsigned long long k = swv[lane];
#pragma unroll
        for (int off = 16; off; off >>= 1) {
          unsigned long long o = __shfl_down_sync(0xffffffffu, k, off);
          k = (o > k) ? o : k;
        }
        if (lane == 0) {
          int w = NN - (int)(k & 0xFFFFu);
          s_w[0] = w;
          g_idx[b * MM + it] = w;
        }
      }
      __syncthreads();
      const int w = s_w[0];
      bx = sax[w]; by = say[w]; bz = saz[w];
    }
  } else {
    // ===================== random-permutation tail =====================
    const int b = blockIdx.x - BB;
    unsigned long long* A = (unsigned long long*)smem_raw;  // NN entries

    for (int r = 0; r < 2; ++r) {
      const uint32_t k0 = pargs.sub[b][r][0];
      const uint32_t k1 = pargs.sub[b][r][1];
      uint32_t keys[8];
#pragma unroll
      for (int t = 0; t < 8; ++t) {
        int i = tid + t * 1024;
        uint32_t y0, y1;
        threefry2x32(k0, k1, 0u, (uint32_t)i, &y0, &y1);
        keys[t] = y0 ^ y1;
      }
#pragma unroll
      for (int t = 0; t < 8; ++t) {
        int i = tid + t * 1024;
        uint32_t v = (r == 0) ? (uint32_t)i : (uint32_t)(A[i] & 0x1FFFull);
        A[i] = ((unsigned long long)keys[t] << 32) |
               ((unsigned long long)(uint32_t)i << 13) | v;
      }
      __syncthreads();
      for (int kk = 2; kk <= NN; kk <<= 1) {
        for (int jj = kk >> 1; jj > 0; jj >>= 1) {
#pragma unroll
          for (int t = 0; t < 8; ++t) {
            int i = tid + t * 1024;
            int ixj = i ^ jj;
            if (ixj > i) {
              bool up = ((i & kk) == 0);
              unsigned long long a = A[i], c = A[ixj];
              if ((a > c) == up) { A[i] = c; A[ixj] = a; }
            }
          }
          __syncthreads();
        }
      }
    }
    for (int t = tid; t < RAND_M; t += 1024)
      g_idx[b * MM + FPS_M + t] = (int)(A[t] & 0x1FFFull);
  }
}

// ---------------------------------------------------------------------------
// KNN + softmax aggregation: WARP-per-center (unchanged — proven fast)
// ---------------------------------------------------------------------------
__global__ __launch_bounds__(256, 2)
void knn_kernel(const float* __restrict__ x, const float* __restrict__ pos,
                float* __restrict__ out) {
  const int warp = threadIdx.x >> 5, lane = threadIdx.x & 31;
  const int b  = blockIdx.x >> 8;
  const int ci = ((blockIdx.x & 255) << 3) + warp;
  const float* px = pos + (size_t)b * 3 * NN;

  __shared__ float sax[2048], say[2048], saz[2048], ssn[2048];

  const int cidx = g_idx[b * MM + ci];
  const float sx = px[cidx], sy = px[NN + cidx], sz = px[2 * NN + cidx];
  const float sm = __fadd_rn(__fadd_rn(__fmul_rn(sx, sx), __fmul_rn(sy, sy)),
                             __fmul_rn(sz, sz));

  float kd[KNNK];
  int   ki[KNNK];
#pragma unroll
  for (int k = 0; k < KNNK; k++) { kd[k] = 3.4e38f; ki[k] = 0; }
  float worstv = 3.4e38f;
  int   worsti = 0, worsts = 0;

  for (int tile = 0; tile < 4; ++tile) {
    __syncthreads();
    const int base = tile * 2048;
    for (int t = threadIdx.x; t < 2048; t += 256) {
      float ax = px[base + t];
      float ay = px[NN + base + t];
      float az = px[2 * NN + base + t];
      sax[t] = ax; say[t] = ay; saz[t] = az;
      ssn[t] = __fadd_rn(__fadd_rn(__fmul_rn(ax, ax), __fmul_rn(ay, ay)),
                         __fmul_rn(az, az));
    }
    __syncthreads();
#pragma unroll 4
    for (int tt = 0; tt < 64; ++tt) {
      const int t = lane + tt * 32;
      float dot = __fadd_rn(
          __fadd_rn(__fmul_rn(sx, sax[t]), __fmul_rn(sy, say[t])),
          __fmul_rn(sz, saz[t]));
      float d2 = __fsub_rn(__fadd_rn(sm, ssn[t]), __fmul_rn(2.0f, dot));
      if (d2 < worstv) {
        const int gi = base + t;
#pragma unroll
        for (int k = 0; k < KNNK; k++)
          if (k == worsts) { kd[k] = d2; ki[k] = gi; }
        worstv = kd[0]; worsti = ki[0]; worsts = 0;
#pragma unroll
        for (int k = 1; k < KNNK; k++) {
          if (kd[k] > worstv || (kd[k] == worstv && ki[k] > worsti)) {
            worstv = kd[k]; worsti = ki[k]; worsts = k;
          }
        }
      }
    }
  }

  unsigned long long Kq[KNNK];
#pragma unroll
  for (int k = 0; k < KNNK; k++)
    Kq[k] = ((unsigned long long)f2ord(kd[k]) << 32) | (uint32_t)ki[k];

  unsigned long long top[KNNK];
#pragma unroll
  for (int r = 0; r < KNNK; ++r) {
    unsigned long long m = Kq[0];
#pragma unroll
    for (int k = 1; k < KNNK; k++) m = (Kq[k] < m) ? Kq[k] : m;
#pragma unroll
    for (int off = 16; off; off >>= 1) {
      unsigned long long o = __shfl_xor_sync(0xffffffffu, m, off);
      m = (o < m) ? o : m;
    }
    top[r] = m;
    bool own = false;
#pragma unroll
    for (int k = 0; k < KNNK; k++) {
      bool hit = (!own && Kq[k] == m);
      if (hit) { Kq[k] = 0xFFFFFFFFFFFFFFFFull; own = true; }
    }
  }

  int   id[KNNK];
  float w[KNNK];
  float maxl = -3.4e38f;
#pragma unroll
  for (int k = 0; k < KNNK; k++) {
    id[k] = (int)(top[k] & 0xFFFFFFFFull);
    float dx = px[id[k]] - sx, dy = px[NN + id[k]] - sy, dz = px[2 * NN + id[k]] - sz;
    float dn = sqrtf(dx * dx + dy * dy + dz * dz);
    dn = fmaxf(dn, 1e-6f);
    float l = -dn / 0.2f;
    w[k] = l;
    maxl = fmaxf(maxl, l);
  }
  float s = 0.0f;
#pragma unroll
  for (int k = 0; k < KNNK; k++) { w[k] = expf(w[k] - maxl); s += w[k]; }
  float inv = 1.0f / s;
#pragma unroll
  for (int k = 0; k < KNNK; k++) w[k] *= inv;

  if (lane == 0) {
    float* outpos = out + (size_t)BB * CC * MM;
    outpos[(size_t)b * 3 * MM + ci] = sx;
    outpos[(size_t)b * 3 * MM + MM + ci] = sy;
    outpos[(size_t)b * 3 * MM + 2 * MM + ci] = sz;
  }

  const float* xb = x + (size_t)b * CC * NN;
  const float* r0 = xb + (size_t)lane * NN;
  const float* r1 = xb + (size_t)(lane + 32) * NN;
  float acc0 = 0.0f, acc1 = 0.0f;
#pragma unroll
  for (int k = 0; k < KNNK; k++) {
    acc0 += w[k] * r0[id[k]];
    acc1 += w[k] * r1[id[k]];
  }
  out[((size_t)b * CC + lane) * MM + ci] = acc0;
  out[((size_t)b * CC + lane + 32) * MM + ci] = acc1;
}

// ---------------------------------------------------------------------------
extern "C" void kernel_launch(void* const* d_in, const int* in_sizes, int n_in,
                              void* d_out, int out_size) {
  const float* x   = (const float*)d_in[0];
  const float* pos = (const float*)d_in[1];
  (void)in_sizes; (void)n_in; (void)out_size;

  FpsArgs fa;
  PermArgs pa;
  compute_consts(&fa, &pa);

  cudaFuncSetAttribute(fused_kernel,
                       cudaFuncAttributeMaxDynamicSharedMemorySize, SMEM_FUSED);

  fused_kernel<<<2 * BB, 1024, SMEM_FUSED>>>(pos, fa, pa);
  knn_kernel<<<BB * 256, 256>>>(x, pos, (float*)d_out);
}

// round 10
// speedup vs baseline: 1.7248x; 1.1943x over previous
#include <cuda_runtime.h>
#include <cstdint>
#include <math.h>

// Problem constants (shapes are fixed by the dataset)
#define BB 8
#define CC 64
#define NN 8192
#define MM 2048
#define KNNK 16
#define FPS_M 1433   // int(2048 * 0.7)
#define RAND_M 615   // 2048 - 1433

#define FT 256               // fused kernel block size (8 warps)
#define FPPT (NN / FT)       // 32 points per thread = 16 f32x2 pairs

// ---------------------------------------------------------------------------
// Threefry-2x32 core (jax threefry2x32 primitive)
// ---------------------------------------------------------------------------
__host__ __device__ __forceinline__ void threefry2x32(
    uint32_t k0, uint32_t k1, uint32_t c0, uint32_t c1,
    uint32_t* o0, uint32_t* o1) {
  uint32_t ks2 = 0x1BD11BDAu ^ k0 ^ k1;
  uint32_t x0 = c0 + k0;
  uint32_t x1 = c1 + k1;
#define TF_ROTL(v, r) (((v) << (r)) | ((v) >> (32 - (r))))
#define TF_ROUND(r) do { x0 += x1; x1 = TF_ROTL(x1, r); x1 ^= x0; } while (0)
  TF_ROUND(13); TF_ROUND(15); TF_ROUND(26); TF_ROUND(6);
  x0 += k1; x1 += ks2 + 1u;
  TF_ROUND(17); TF_ROUND(29); TF_ROUND(16); TF_ROUND(24);
  x0 += ks2; x1 += k0 + 2u;
  TF_ROUND(13); TF_ROUND(15); TF_ROUND(26); TF_ROUND(6);
  x0 += k0; x1 += k1 + 3u;
  TF_ROUND(17); TF_ROUND(29); TF_ROUND(16); TF_ROUND(24);
  x0 += k1; x1 += ks2 + 4u;
  TF_ROUND(13); TF_ROUND(15); TF_ROUND(26); TF_ROUND(6);
  x0 += ks2; x1 += k0 + 5u;
#undef TF_ROUND
#undef TF_ROTL
  *o0 = x0; *o1 = x1;
}

struct FpsArgs  { int start[BB]; };
struct PermArgs { uint32_t sub[BB][2][2]; };

__device__ int g_idx[BB * MM];

// ---------------------------------------------------------------------------
// Packed f32x2 helpers (bit-exact per-lane .rn semantics, sm_103a)
// ---------------------------------------------------------------------------
__device__ __forceinline__ unsigned long long f2_pack(float lo, float hi) {
  unsigned long long o;
  asm("mov.b64 %0, {%1, %2};" : "=l"(o) : "f"(lo), "f"(hi));
  return o;
}
__device__ __forceinline__ void f2_unpack(unsigned long long v, float* lo, float* hi) {
  asm("mov.b64 {%0, %1}, %2;" : "=f"(*lo), "=f"(*hi) : "l"(v));
}
__device__ __forceinline__ unsigned long long f2_add(unsigned long long a,
                                                     unsigned long long b) {
  unsigned long long o;
  asm("add.rn.f32x2 %0, %1, %2;" : "=l"(o) : "l"(a), "l"(b));
  return o;
}
__device__ __forceinline__ unsigned long long f2_mul(unsigned long long a,
                                                     unsigned long long b) {
  unsigned long long o;
  asm("mul.rn.f32x2 %0, %1, %2;" : "=l"(o) : "l"(a), "l"(b));
  return o;
}

// monotone map: float bits -> u32 preserving float ordering (handles negatives)
__device__ __forceinline__ uint32_t f2ord(float f) {
  uint32_t u = __float_as_uint(f);
  return u ^ ((u & 0x80000000u) ? 0xFFFFFFFFu : 0x80000000u);
}

// ---------------------------------------------------------------------------
// Host-side PRNG derivation — PARTITIONABLE threefry semantics
// ---------------------------------------------------------------------------
static void compute_consts(FpsArgs* fa, PermArgs* pa) {
  for (int b = 0; b < BB; b++) {
    uint32_t fk0, fk1;
    threefry2x32(0u, 42u, 0u, (uint32_t)b, &fk0, &fk1);
    uint32_t k20, k21;
    threefry2x32(fk0, fk1, 0u, 1u, &k20, &k21);
    uint32_t s0, s1;
    threefry2x32(k20, k21, 0u, 0u, &s0, &s1);
    fa->start[b] = (int)((s0 ^ s1) & (NN - 1));
  }
  uint32_t rk0, rk1;
  threefry2x32(0u, 42u, 0u, 1u, &rk0, &rk1);
  for (int b = 0; b < BB; b++) {
    uint32_t k0, k1;
    threefry2x32(rk0, rk1, 0u, (uint32_t)b, &k0, &k1);
    for (int r = 0; r < 2; r++) {
      uint32_t n0, n1, c0, c1;
      threefry2x32(k0, k1, 0u, 0u, &n0, &n1);
      threefry2x32(k0, k1, 0u, 1u, &c0, &c1);
      pa->sub[b][r][0] = c0;
      pa->sub[b][r][1] = c1;
      k0 = n0; k1 = n1;
    }
  }
}

// Fused FPS + permutation kernel, 256 threads/block (255-reg budget, no spill).
// Blocks 0..7 = FPS(batch), 8..15 = perm(batch).
#define SMEM_FUSED (3 * NN * 4 + 4 * 32 * 4 + 64)

__global__ __launch_bounds__(FT, 1)
void fused_kernel(const float* __restrict__ pos, FpsArgs fargs, PermArgs pargs) {
  extern __shared__ char smem_raw[];
  const int tid = threadIdx.x;

  if (blockIdx.x < BB) {
    // ===================== FPS: 8 warps, 32 pts/thread in regs ==============
    const int b = blockIdx.x;
    float* sax = (float*)smem_raw;
    float* say = sax + NN;
    float* saz = say + NN;
    uint32_t* swval = (uint32_t*)(saz + NN);   // [2][8] (parity double-buffer)
    uint32_t* swidx = swval + 32;              // [2][8]

    const float* px = pos + (size_t)b * 3 * NN;
    const float* py = px + NN;
    const float* pz = px + 2 * NN;

    unsigned long long rx2[16], ry2[16], rz2[16];
    float rd[32];
#pragma unroll
    for (int j = 0; j < 16; j++) {
      int i0 = (2 * j) * FT + tid;
      int i1 = i0 + FT;
      float x0 = px[i0], x1 = px[i1];
      float y0 = py[i0], y1 = py[i1];
      float z0 = pz[i0], z1 = pz[i1];
      rx2[j] = f2_pack(x0, x1);
      ry2[j] = f2_pack(y0, y1);
      rz2[j] = f2_pack(z0, z1);
      sax[i0] = x0; sax[i1] = x1;
      say[i0] = y0; say[i1] = y1;
      saz[i0] = z0; saz[i1] = z1;
      rd[2 * j] = 1e10f; rd[2 * j + 1] = 1e10f;
    }
    __syncthreads();

    const int start = fargs.start[b];
    if (tid == 0) g_idx[b * MM] = start;
    float bx = sax[start], by = say[start], bz = saz[start];

    const int lane = tid & 31, warp = tid >> 5;
    int par = 0;

    for (int it = 1; it < FPS_M; ++it) {
      unsigned long long nbx2 = f2_pack(-bx, -bx);
      unsigned long long nby2 = f2_pack(-by, -by);
      unsigned long long nbz2 = f2_pack(-bz, -bz);

      float bestv = -1.0f;
      int   besti = 0;
#pragma unroll
      for (int j = 0; j < 16; j++) {
        unsigned long long dx2 = f2_add(rx2[j], nbx2);
        unsigned long long dy2 = f2_add(ry2[j], nby2);
        unsigned long long dz2 = f2_add(rz2[j], nbz2);
        unsigned long long dd2 =
            f2_add(f2_add(f2_mul(dx2, dx2), f2_mul(dy2, dy2)), f2_mul(dz2, dz2));
        float d0, d1;
        f2_unpack(dd2, &d0, &d1);
        float nv0 = fminf(rd[2 * j], d0);
        rd[2 * j] = nv0;
        if (nv0 > bestv) { bestv = nv0; besti = (2 * j) * FT + tid; }
        float nv1 = fminf(rd[2 * j + 1], d1);
        rd[2 * j + 1] = nv1;
        if (nv1 > bestv) { bestv = nv1; besti = (2 * j + 1) * FT + tid; }
      }
      // warp argmax via redux: distances >= 0 -> float bits monotone in value;
      // ties resolved to the lowest index by the min-redux over candidates.
      uint32_t bits = __float_as_uint(bestv);
      uint32_t wmax = __reduce_max_sync(0xffffffffu, bits);
      uint32_t cand = (bits == wmax) ? (uint32_t)besti : 0xFFFFFFFFu;
      uint32_t wi   = __reduce_min_sync(0xffffffffu, cand);
      if (lane == 0) { swval[par * 8 + warp] = wmax; swidx[par * 8 + warp] = wi; }
      __syncthreads();
      // all 8 warps reduce the 8 partials: 2 predicated LDS + 2 redux each
      uint32_t v    = (lane < 8) ? swval[par * 8 + lane] : 0u;
      uint32_t bmax = __reduce_max_sync(0xffffffffu, v);
      uint32_t bc   = (lane < 8 && v == bmax) ? swidx[par * 8 + lane] : 0xFFFFFFFFu;
      uint32_t w    = __reduce_min_sync(0xffffffffu, bc);
      if (tid == 0) g_idx[b * MM + it] = (int)w;
      bx = sax[w]; by = say[w]; bz = saz[w];
      par ^= 1;
    }
  } else {
    // ===================== random-permutation tail (256 thr) ================
    const int b = blockIdx.x - BB;
    unsigned long long* A = (unsigned long long*)smem_raw;  // NN entries

    for (int r = 0; r < 2; ++r) {
      const uint32_t k0 = pargs.sub[b][r][0];
      const uint32_t k1 = pargs.sub[b][r][1];
#pragma unroll 4
      for (int t = 0; t < 32; ++t) {
        int i = tid + t * FT;
        uint32_t y0, y1;
        threefry2x32(k0, k1, 0u, (uint32_t)i, &y0, &y1);
        uint32_t kk = y0 ^ y1;
        uint32_t v = (r == 0) ? (uint32_t)i : (uint32_t)(A[i] & 0x1FFFull);
        unsigned long long e = ((unsigned long long)kk << 32) |
                               ((unsigned long long)(uint32_t)i << 13) | v;
        if (r == 0) {
          A[i] = e;
        } else {
          __syncthreads();  // no-op alignment barrier avoided; see below
          A[i] = e;
        }
      }
      __syncthreads();
      for (int kk2 = 2; kk2 <= NN; kk2 <<= 1) {
        for (int jj = kk2 >> 1; jj > 0; jj >>= 1) {
#pragma unroll 4
          for (int t = 0; t < 32; ++t) {
            int i = tid + t * FT;
            int ixj = i ^ jj;
            if (ixj > i) {
              bool up = ((i & kk2) == 0);
              unsigned long long a = A[i], c = A[ixj];
              if ((a > c) == up) { A[i] = c; A[ixj] = a; }
            }
          }
          __syncthreads();
        }
      }
    }
    for (int t = tid; t < RAND_M; t += FT)
      g_idx[b * MM + FPS_M + t] = (int)(A[t] & 0x1FFFull);
  }
}

// ---------------------------------------------------------------------------
// KNN + softmax aggregation: WARP-per-center (unchanged — proven fast)
// ---------------------------------------------------------------------------
__global__ __launch_bounds__(256, 2)
void knn_kernel(const float* __restrict__ x, const float* __restrict__ pos,
                float* __restrict__ out) {
  const int warp = threadIdx.x >> 5, lane = threadIdx.x & 31;
  const int b  = blockIdx.x >> 8;
  const int ci = ((blockIdx.x & 255) << 3) + warp;
  const float* px = pos + (size_t)b * 3 * NN;

  __shared__ float sax[2048], say[2048], saz[2048], ssn[2048];

  const int cidx = g_idx[b * MM + ci];
  const float sx = px[cidx], sy = px[NN + cidx], sz = px[2 * NN + cidx];
  const float sm = __fadd_rn(__fadd_rn(__fmul_rn(sx, sx), __fmul_rn(sy, sy)),
                             __fmul_rn(sz, sz));

  float kd[KNNK];
  int   ki[KNNK];
#pragma unroll
  for (int k = 0; k < KNNK; k++) { kd[k] = 3.4e38f; ki[k] = 0; }
  float worstv = 3.4e38f;
  int   worsti = 0, worsts = 0;

  for (int tile = 0; tile < 4; ++tile) {
    __syncthreads();
    const int base = tile * 2048;
    for (int t = threadIdx.x; t < 2048; t += 256) {
      float ax = px[base + t];
      float ay = px[NN + base + t];
      float az = px[2 * NN + base + t];
      sax[t] = ax; say[t] = ay; saz[t] = az;
      ssn[t] = __fadd_rn(__fadd_rn(__fmul_rn(ax, ax), __fmul_rn(ay, ay)),
                         __fmul_rn(az, az));
    }
    __syncthreads();
#pragma unroll 4
    for (int tt = 0; tt < 64; ++tt) {
      const int t = lane + tt * 32;
      float dot = __fadd_rn(
          __fadd_rn(__fmul_rn(sx, sax[t]), __fmul_rn(sy, say[t])),
          __fmul_rn(sz, saz[t]));
      float d2 = __fsub_rn(__fadd_rn(sm, ssn[t]), __fmul_rn(2.0f, dot));
      if (d2 < worstv) {
        const int gi = base + t;
#pragma unroll
        for (int k = 0; k < KNNK; k++)
          if (k == worsts) { kd[k] = d2; ki[k] = gi; }
        worstv = kd[0]; worsti = ki[0]; worsts = 0;
#pragma unroll
        for (int k = 1; k < KNNK; k++) {
          if (kd[k] > worstv || (kd[k] == worstv && ki[k] > worsti)) {
            worstv = kd[k]; worsti = ki[k]; worsts = k;
          }
        }
      }
    }
  }

  unsigned long long Kq[KNNK];
#pragma unroll
  for (int k = 0; k < KNNK; k++)
    Kq[k] = ((unsigned long long)f2ord(kd[k]) << 32) | (uint32_t)ki[k];

  unsigned long long top[KNNK];
#pragma unroll
  for (int r = 0; r < KNNK; ++r) {
    unsigned long long m = Kq[0];
#pragma unroll
    for (int k = 1; k < KNNK; k++) m = (Kq[k] < m) ? Kq[k] : m;
#pragma unroll
    for (int off = 16; off; off >>= 1) {
      unsigned long long o = __shfl_xor_sync(0xffffffffu, m, off);
      m = (o < m) ? o : m;
    }
    top[r] = m;
    bool own = false;
#pragma unroll
    for (int k = 0; k < KNNK; k++) {
      bool hit = (!own && Kq[k] == m);
      if (hit) { Kq[k] = 0xFFFFFFFFFFFFFFFFull; own = true; }
    }
  }

  int   id[KNNK];
  float w[KNNK];
  float maxl = -3.4e38f;
#pragma unroll
  for (int k = 0; k < KNNK; k++) {
    id[k] = (int)(top[k] & 0xFFFFFFFFull);
    float dx = px[id[k]] - sx, dy = px[NN + id[k]] - sy, dz = px[2 * NN + id[k]] - sz;
    float dn = sqrtf(dx * dx + dy * dy + dz * dz);
    dn = fmaxf(dn, 1e-6f);
    float l = -dn / 0.2f;
    w[k] = l;
    maxl = fmaxf(maxl, l);
  }
  float s = 0.0f;
#pragma unroll
  for (int k = 0; k < KNNK; k++) { w[k] = expf(w[k] - maxl); s += w[k]; }
  float inv = 1.0f / s;
#pragma unroll
  for (int k = 0; k < KNNK; k++) w[k] *= inv;

  if (lane == 0) {
    float* outpos = out + (size_t)BB * CC * MM;
    outpos[(size_t)b * 3 * MM + ci] = sx;
    outpos[(size_t)b * 3 * MM + MM + ci] = sy;
    outpos[(size_t)b * 3 * MM + 2 * MM + ci] = sz;
  }

  const float* xb = x + (size_t)b * CC * NN;
  const float* r0 = xb + (size_t)lane * NN;
  const float* r1 = xb + (size_t)(lane + 32) * NN;
  float acc0 = 0.0f, acc1 = 0.0f;
#pragma unroll
  for (int k = 0; k < KNNK; k++) {
    acc0 += w[k] * r0[id[k]];
    acc1 += w[k] * r1[id[k]];
  }
  out[((size_t)b * CC + lane) * MM + ci] = acc0;
  out[((size_t)b * CC + lane + 32) * MM + ci] = acc1;
}

// ---------------------------------------------------------------------------
extern "C" void kernel_launch(void* const* d_in, const int* in_sizes, int n_in,
                              void* d_out, int out_size) {
  const float* x   = (const float*)d_in[0];
  const float* pos = (const float*)d_in[1];
  (void)in_sizes; (void)n_in; (void)out_size;

  FpsArgs fa;
  PermArgs pa;
  compute_consts(&fa, &pa);

  cudaFuncSetAttribute(fused_kernel,
                       cudaFuncAttributeMaxDynamicSharedMemorySize, SMEM_FUSED);

  fused_kernel<<<2 * BB, FT, SMEM_FUSED>>>(pos, fa, pa);
  knn_kernel<<<BB * 256, 256>>>(x, pos, (float*)d_out);
}

// round 11
// speedup vs baseline: 4.0210x; 2.3312x over previous
#include <cuda_runtime.h>
#include <cstdint>
#include <math.h>

// Problem constants (shapes are fixed by the dataset)
#define BB 8
#define CC 64
#define NN 8192
#define MM 2048
#define KNNK 16
#define FPS_M 1433   // int(2048 * 0.7)
#define RAND_M 615   // 2048 - 1433

#define FT 256               // fused kernel block size (8 warps)
#define INF64 0xFFFFFFFFFFFFFFFFull

// ---------------------------------------------------------------------------
// Threefry-2x32 core (jax threefry2x32 primitive)
// ---------------------------------------------------------------------------
__host__ __device__ __forceinline__ void threefry2x32(
    uint32_t k0, uint32_t k1, uint32_t c0, uint32_t c1,
    uint32_t* o0, uint32_t* o1) {
  uint32_t ks2 = 0x1BD11BDAu ^ k0 ^ k1;
  uint32_t x0 = c0 + k0;
  uint32_t x1 = c1 + k1;
#define TF_ROTL(v, r) (((v) << (r)) | ((v) >> (32 - (r))))
#define TF_ROUND(r) do { x0 += x1; x1 = TF_ROTL(x1, r); x1 ^= x0; } while (0)
  TF_ROUND(13); TF_ROUND(15); TF_ROUND(26); TF_ROUND(6);
  x0 += k1; x1 += ks2 + 1u;
  TF_ROUND(17); TF_ROUND(29); TF_ROUND(16); TF_ROUND(24);
  x0 += ks2; x1 += k0 + 2u;
  TF_ROUND(13); TF_ROUND(15); TF_ROUND(26); TF_ROUND(6);
  x0 += k0; x1 += k1 + 3u;
  TF_ROUND(17); TF_ROUND(29); TF_ROUND(16); TF_ROUND(24);
  x0 += k1; x1 += ks2 + 4u;
  TF_ROUND(13); TF_ROUND(15); TF_ROUND(26); TF_ROUND(6);
  x0 += ks2; x1 += k0 + 5u;
#undef TF_ROUND
#undef TF_ROTL
  *o0 = x0; *o1 = x1;
}

struct FpsArgs  { int start[BB]; };
struct PermArgs { uint32_t sub[BB][2][2]; };

__device__ int g_idx[BB * MM];
__device__ float4 g_pack[BB * NN];   // (x, y, z, ||p||^2) per point

// ---------------------------------------------------------------------------
// Packed f32x2 helpers (bit-exact per-lane .rn semantics, sm_103a)
// ---------------------------------------------------------------------------
__device__ __forceinline__ unsigned long long f2_pack(float lo, float hi) {
  unsigned long long o;
  asm("mov.b64 %0, {%1, %2};" : "=l"(o) : "f"(lo), "f"(hi));
  return o;
}
__device__ __forceinline__ void f2_unpack(unsigned long long v, float* lo, float* hi) {
  asm("mov.b64 {%0, %1}, %2;" : "=f"(*lo), "=f"(*hi) : "l"(v));
}
__device__ __forceinline__ unsigned long long f2_add(unsigned long long a,
                                                     unsigned long long b) {
  unsigned long long o;
  asm("add.rn.f32x2 %0, %1, %2;" : "=l"(o) : "l"(a), "l"(b));
  return o;
}
__device__ __forceinline__ unsigned long long f2_mul(unsigned long long a,
                                                     unsigned long long b) {
  unsigned long long o;
  asm("mul.rn.f32x2 %0, %1, %2;" : "=l"(o) : "l"(a), "l"(b));
  return o;
}

// monotone map: float bits -> u32 preserving float ordering (handles negatives)
__device__ __forceinline__ uint32_t f2ord(float f) {
  uint32_t u = __float_as_uint(f);
  return u ^ ((u & 0x80000000u) ? 0xFFFFFFFFu : 0x80000000u);
}

// ---------------------------------------------------------------------------
// Host-side PRNG derivation — PARTITIONABLE threefry semantics
// ---------------------------------------------------------------------------
static void compute_consts(FpsArgs* fa, PermArgs* pa) {
  for (int b = 0; b < BB; b++) {
    uint32_t fk0, fk1;
    threefry2x32(0u, 42u, 0u, (uint32_t)b, &fk0, &fk1);
    uint32_t k20, k21;
    threefry2x32(fk0, fk1, 0u, 1u, &k20, &k21);
    uint32_t s0, s1;
    threefry2x32(k20, k21, 0u, 0u, &s0, &s1);
    fa->start[b] = (int)((s0 ^ s1) & (NN - 1));
  }
  uint32_t rk0, rk1;
  threefry2x32(0u, 42u, 0u, 1u, &rk0, &rk1);
  for (int b = 0; b < BB; b++) {
    uint32_t k0, k1;
    threefry2x32(rk0, rk1, 0u, (uint32_t)b, &k0, &k1);
    for (int r = 0; r < 2; r++) {
      uint32_t n0, n1, c0, c1;
      threefry2x32(k0, k1, 0u, 0u, &n0, &n1);
      threefry2x32(k0, k1, 0u, 1u, &c0, &c1);
      pa->sub[b][r][0] = c0;
      pa->sub[b][r][1] = c1;
      k0 = n0; k1 = n1;
    }
  }
}

// ---------------------------------------------------------------------------
// Pre-pack kernel: g_pack[b][i] = (x, y, z, sn) with sn in reference op-order
// ---------------------------------------------------------------------------
__global__ __launch_bounds__(1024, 1)
void prepack_kernel(const float* __restrict__ pos) {
  const int b = blockIdx.x;
  const float* px = pos + (size_t)b * 3 * NN;
  const float* py = px + NN;
  const float* pz = px + 2 * NN;
  for (int i = threadIdx.x; i < NN; i += 1024) {
    float xx = px[i], yy = py[i], zz = pz[i];
    float sn = __fadd_rn(__fadd_rn(__fmul_rn(xx, xx), __fmul_rn(yy, yy)),
                         __fmul_rn(zz, zz));
    g_pack[b * NN + i] = make_float4(xx, yy, zz, sn);
  }
}

// Fused FPS + permutation kernel — UNCHANGED from R10 (best measured fused).
#define SMEM_FUSED (3 * NN * 4 + 4 * 32 * 4 + 64)

__global__ __launch_bounds__(FT, 1)
void fused_kernel(const float* __restrict__ pos, FpsArgs fargs, PermArgs pargs) {
  extern __shared__ char smem_raw[];
  const int tid = threadIdx.x;

  if (blockIdx.x < BB) {
    const int b = blockIdx.x;
    float* sax = (float*)smem_raw;
    float* say = sax + NN;
    float* saz = say + NN;
    uint32_t* swval = (uint32_t*)(saz + NN);   // [2][8]
    uint32_t* swidx = swval + 32;              // [2][8]

    const float* px = pos + (size_t)b * 3 * NN;
    const float* py = px + NN;
    const float* pz = px + 2 * NN;

    unsigned long long rx2[16], ry2[16], rz2[16];
    float rd[32];
#pragma unroll
    for (int j = 0; j < 16; j++) {
      int i0 = (2 * j) * FT + tid;
      int i1 = i0 + FT;
      float x0 = px[i0], x1 = px[i1];
      float y0 = py[i0], y1 = py[i1];
      float z0 = pz[i0], z1 = pz[i1];
      rx2[j] = f2_pack(x0, x1);
      ry2[j] = f2_pack(y0, y1);
      rz2[j] = f2_pack(z0, z1);
      sax[i0] = x0; sax[i1] = x1;
      say[i0] = y0; say[i1] = y1;
      saz[i0] = z0; saz[i1] = z1;
      rd[2 * j] = 1e10f; rd[2 * j + 1] = 1e10f;
    }
    __syncthreads();

    const int start = fargs.start[b];
    if (tid == 0) g_idx[b * MM] = start;
    float bx = sax[start], by = say[start], bz = saz[start];

    const int lane = tid & 31, warp = tid >> 5;
    int par = 0;

    for (int it = 1; it < FPS_M; ++it) {
      unsigned long long nbx2 = f2_pack(-bx, -bx);
      unsigned long long nby2 = f2_pack(-by, -by);
      unsigned long long nbz2 = f2_pack(-bz, -bz);

      float bestv = -1.0f;
      int   besti = 0;
#pragma unroll
      for (int j = 0; j < 16; j++) {
        unsigned long long dx2 = f2_add(rx2[j], nbx2);
        unsigned long long dy2 = f2_add(ry2[j], nby2);
        unsigned long long dz2 = f2_add(rz2[j], nbz2);
        unsigned long long dd2 =
            f2_add(f2_add(f2_mul(dx2, dx2), f2_mul(dy2, dy2)), f2_mul(dz2, dz2));
        float d0, d1;
        f2_unpack(dd2, &d0, &d1);
        float nv0 = fminf(rd[2 * j], d0);
        rd[2 * j] = nv0;
        if (nv0 > bestv) { bestv = nv0; besti = (2 * j) * FT + tid; }
        float nv1 = fminf(rd[2 * j + 1], d1);
        rd[2 * j + 1] = nv1;
        if (nv1 > bestv) { bestv = nv1; besti = (2 * j + 1) * FT + tid; }
      }
      uint32_t bits = __float_as_uint(bestv);
      uint32_t wmax = __reduce_max_sync(0xffffffffu, bits);
      uint32_t cand = (bits == wmax) ? (uint32_t)besti : 0xFFFFFFFFu;
      uint32_t wi   = __reduce_min_sync(0xffffffffu, cand);
      if (lane == 0) { swval[par * 8 + warp] = wmax; swidx[par * 8 + warp] = wi; }
      __syncthreads();
      uint32_t v    = (lane < 8) ? swval[par * 8 + lane] : 0u;
      uint32_t bmax = __reduce_max_sync(0xffffffffu, v);
      uint32_t bc   = (lane < 8 && v == bmax) ? swidx[par * 8 + lane] : 0xFFFFFFFFu;
      uint32_t w    = __reduce_min_sync(0xffffffffu, bc);
      if (tid == 0) g_idx[b * MM + it] = (int)w;
      bx = sax[w]; by = say[w]; bz = saz[w];
      par ^= 1;
    }
  } else {
    const int b = blockIdx.x - BB;
    unsigned long long* A = (unsigned long long*)smem_raw;

    for (int r = 0; r < 2; ++r) {
      const uint32_t k0 = pargs.sub[b][r][0];
      const uint32_t k1 = pargs.sub[b][r][1];
#pragma unroll 4
      for (int t = 0; t < 32; ++t) {
        int i = tid + t * FT;
        uint32_t y0, y1;
        threefry2x32(k0, k1, 0u, (uint32_t)i, &y0, &y1);
        uint32_t kk = y0 ^ y1;
        uint32_t v = (r == 0) ? (uint32_t)i : (uint32_t)(A[i] & 0x1FFFull);
        A[i] = ((unsigned long long)kk << 32) |
               ((unsigned long long)(uint32_t)i << 13) | v;
      }
      __syncthreads();
      for (int kk2 = 2; kk2 <= NN; kk2 <<= 1) {
        for (int jj = kk2 >> 1; jj > 0; jj >>= 1) {
#pragma unroll 4
          for (int t = 0; t < 32; ++t) {
            int i = tid + t * FT;
            int ixj = i ^ jj;
            if (ixj > i) {
              bool up = ((i & kk2) == 0);
              unsigned long long a = A[i], c = A[ixj];
              if ((a > c) == up) { A[i] = c; A[ixj] = a; }
            }
          }
          __syncthreads();
        }
      }
    }
    for (int t = tid; t < RAND_M; t += FT)
      g_idx[b * MM + FPS_M + t] = (int)(A[t] & 0x1FFFull);
  }
}

// ---------------------------------------------------------------------------
// merge16: exact 16-smallest of {cur (distributed), cand (distributed)} via
// 16-round warp min-extraction; rebuilds distributed cur and threshold tauf.
// Keys are (f2ord(d2)<<32)|idx — unique (idx unique), INF64 = empty sentinel.
// ---------------------------------------------------------------------------
__device__ __forceinline__ void merge16(unsigned long long& cur,
                                        unsigned long long cand,
                                        unsigned long long* top,
                                        float& tauf, int lane) {
#pragma unroll
  for (int r = 0; r < KNNK; ++r) {
    unsigned long long m = (cur < cand) ? cur : cand;
#pragma unroll
    for (int off = 16; off; off >>= 1) {
      unsigned long long o = __shfl_xor_sync(0xffffffffu, m, off);
      m = (o < m) ? o : m;
    }
    top[r] = m;
    if (cur == m) cur = INF64;
    else if (cand == m) cand = INF64;
  }
  cur = (lane < KNNK) ? top[lane] : INF64;
  unsigned long long t15 = top[15];
  if (t15 == INF64) {
    tauf = __int_as_float(0x7f800000);  // +inf
  } else {
    uint32_t v = (uint32_t)(t15 >> 32);
    uint32_t bits = (v & 0x80000000u) ? (v ^ 0x80000000u) : ~v;
    tauf = __uint_as_float(bits);       // exact inverse of f2ord
  }
}

// ---------------------------------------------------------------------------
// KNN v3: warp-per-center, threshold-gated streaming selection.
// Hot loop is warp-uniform; rare qualifiers buffered + merged exactly.
// ---------------------------------------------------------------------------
__global__ __launch_bounds__(256, 2)
void knn_kernel(const float* __restrict__ x, const float* __restrict__ pos,
                float* __restrict__ out) {
  __shared__ unsigned long long sbuf[8][64];
  const int warp = threadIdx.x >> 5, lane = threadIdx.x & 31;
  const int b  = blockIdx.x >> 8;
  const int ci = ((blockIdx.x & 255) << 3) + warp;
  const float* px = pos + (size_t)b * 3 * NN;
  const float4* pk = g_pack + (size_t)b * NN;

  const int cidx = g_idx[b * MM + ci];
  const float4 cc = pk[cidx];
  const float sx = cc.x, sy = cc.y, sz = cc.z, sm = cc.w;

  unsigned long long top[KNNK];
  unsigned long long cur;
  float tauf;

  // step 0: first 32 points seed the exact top-16 + threshold
  {
    float4 p = pk[lane];
    float dot = __fadd_rn(
        __fadd_rn(__fmul_rn(sx, p.x), __fmul_rn(sy, p.y)), __fmul_rn(sz, p.z));
    float d2 = __fsub_rn(__fadd_rn(sm, p.w), __fmul_rn(2.0f, dot));
    cur = ((unsigned long long)f2ord(d2) << 32) | (uint32_t)lane;
    merge16(cur, INF64, top, tauf, lane);
  }

  unsigned long long* buf = sbuf[warp];
  int base = 0;
  const uint32_t ltmask = (lane == 31) ? 0x7FFFFFFFu : ((1u << lane) - 1u);

#pragma unroll 2
  for (int s = 1; s < NN / 32; ++s) {
    const int i = (s << 5) | lane;
    float4 p = pk[i];
    float dot = __fadd_rn(
        __fadd_rn(__fmul_rn(sx, p.x), __fmul_rn(sy, p.y)), __fmul_rn(sz, p.z));
    float d2 = __fsub_rn(__fadd_rn(sm, p.w), __fmul_rn(2.0f, dot));
    bool pred = (d2 <= tauf);   // superset of true top-16 updates (ties incl.)
    uint32_t mask = __ballot_sync(0xffffffffu, pred);
    if (mask) {
      int pre = __popc(mask & ltmask);
      if (pred)
        buf[base + pre] =
            ((unsigned long long)f2ord(d2) << 32) | (uint32_t)i;
      base += __popc(mask);
      __syncwarp();
      while (base >= 32) {
        unsigned long long cand = buf[lane];
        merge16(cur, cand, top, tauf, lane);
        base -= 32;
        unsigned long long t = (lane < base) ? buf[32 + lane] : 0ull;
        __syncwarp();
        if (lane < base) buf[lane] = t;
        __syncwarp();
      }
    }
  }
  if (base > 0) {
    __syncwarp();
    unsigned long long cand = (lane < base) ? buf[lane] : INF64;
    merge16(cur, cand, top, tauf, lane);
  }

  // softmax over exact euclidean distances (same ops as reference)
  int   id[KNNK];
  float w[KNNK];
  float maxl = -3.4e38f;
#pragma unroll
  for (int k = 0; k < KNNK; k++) {
    id[k] = (int)(top[k] & 0xFFFFFFFFull);
    float dx = px[id[k]] - sx, dy = px[NN + id[k]] - sy, dz = px[2 * NN + id[k]] - sz;
    float dn = sqrtf(dx * dx + dy * dy + dz * dz);
    dn = fmaxf(dn, 1e-6f);
    float l = -dn / 0.2f;
    w[k] = l;
    maxl = fmaxf(maxl, l);
  }
  float s = 0.0f;
#pragma unroll
  for (int k = 0; k < KNNK; k++) { w[k] = expf(w[k] - maxl); s += w[k]; }
  float inv = 1.0f / s;
#pragma unroll
  for (int k = 0; k < KNNK; k++) w[k] *= inv;

  if (lane == 0) {
    float* outpos = out + (size_t)BB * CC * MM;
    outpos[(size_t)b * 3 * MM + ci] = sx;
    outpos[(size_t)b * 3 * MM + MM + ci] = sy;
    outpos[(size_t)b * 3 * MM + 2 * MM + ci] = sz;
  }

  const float* xb = x + (size_t)b * CC * NN;
  const float* r0 = xb + (size_t)lane * NN;
  const float* r1 = xb + (size_t)(lane + 32) * NN;
  float acc0 = 0.0f, acc1 = 0.0f;
#pragma unroll
  for (int k = 0; k < KNNK; k++) {
    acc0 += w[k] * r0[id[k]];
    acc1 += w[k] * r1[id[k]];
  }
  out[((size_t)b * CC + lane) * MM + ci] = acc0;
  out[((size_t)b * CC + lane + 32) * MM + ci] = acc1;
}

// ---------------------------------------------------------------------------
extern "C" void kernel_launch(void* const* d_in, const int* in_sizes, int n_in,
                              void* d_out, int out_size) {
  const float* x   = (const float*)d_in[0];
  const float* pos = (const float*)d_in[1];
  (void)in_sizes; (void)n_in; (void)out_size;

  FpsArgs fa;
  PermArgs pa;
  compute_consts(&fa, &pa);

  cudaFuncSetAttribute(fused_kernel,
                       cudaFuncAttributeMaxDynamicSharedMemorySize, SMEM_FUSED);

  prepack_kernel<<<BB, 1024>>>(pos);
  fused_kernel<<<2 * BB, FT, SMEM_FUSED>>>(pos, fa, pa);
  knn_kernel<<<BB * 256, 256>>>(x, pos, (float*)d_out);
}

// round 12
// speedup vs baseline: 4.0451x; 1.0060x over previous
#include <cuda_runtime.h>
#include <cstdint>
#include <math.h>

// Problem constants (shapes are fixed by the dataset)
#define BB 8
#define CC 64
#define NN 8192
#define MM 2048
#define KNNK 16
#define FPS_M 1433   // int(2048 * 0.7)
#define RAND_M 615   // 2048 - 1433

#define FT 256               // fused kernel block size (8 warps)
#define INF64 0xFFFFFFFFFFFFFFFFull

// ---------------------------------------------------------------------------
// Threefry-2x32 core (jax threefry2x32 primitive)
// ---------------------------------------------------------------------------
__host__ __device__ __forceinline__ void threefry2x32(
    uint32_t k0, uint32_t k1, uint32_t c0, uint32_t c1,
    uint32_t* o0, uint32_t* o1) {
  uint32_t ks2 = 0x1BD11BDAu ^ k0 ^ k1;
  uint32_t x0 = c0 + k0;
  uint32_t x1 = c1 + k1;
#define TF_ROTL(v, r) (((v) << (r)) | ((v) >> (32 - (r))))
#define TF_ROUND(r) do { x0 += x1; x1 = TF_ROTL(x1, r); x1 ^= x0; } while (0)
  TF_ROUND(13); TF_ROUND(15); TF_ROUND(26); TF_ROUND(6);
  x0 += k1; x1 += ks2 + 1u;
  TF_ROUND(17); TF_ROUND(29); TF_ROUND(16); TF_ROUND(24);
  x0 += ks2; x1 += k0 + 2u;
  TF_ROUND(13); TF_ROUND(15); TF_ROUND(26); TF_ROUND(6);
  x0 += k0; x1 += k1 + 3u;
  TF_ROUND(17); TF_ROUND(29); TF_ROUND(16); TF_ROUND(24);
  x0 += k1; x1 += ks2 + 4u;
  TF_ROUND(13); TF_ROUND(15); TF_ROUND(26); TF_ROUND(6);
  x0 += ks2; x1 += k0 + 5u;
#undef TF_ROUND
#undef TF_ROTL
  *o0 = x0; *o1 = x1;
}

struct FpsArgs  { int start[BB]; };
struct PermArgs { uint32_t sub[BB][2][2]; };

__device__ int g_idx[BB * MM];
__device__ float4 g_pack[BB * NN];   // (x, y, z, ||p||^2) per point

// ---------------------------------------------------------------------------
// Packed f32x2 helpers (bit-exact per-lane .rn semantics, sm_103a)
// ---------------------------------------------------------------------------
__device__ __forceinline__ unsigned long long f2_pack(float lo, float hi) {
  unsigned long long o;
  asm("mov.b64 %0, {%1, %2};" : "=l"(o) : "f"(lo), "f"(hi));
  return o;
}
__device__ __forceinline__ void f2_unpack(unsigned long long v, float* lo, float* hi) {
  asm("mov.b64 {%0, %1}, %2;" : "=f"(*lo), "=f"(*hi) : "l"(v));
}
__device__ __forceinline__ unsigned long long f2_add(unsigned long long a,
                                                     unsigned long long b) {
  unsigned long long o;
  asm("add.rn.f32x2 %0, %1, %2;" : "=l"(o) : "l"(a), "l"(b));
  return o;
}
__device__ __forceinline__ unsigned long long f2_mul(unsigned long long a,
                                                     unsigned long long b) {
  unsigned long long o;
  asm("mul.rn.f32x2 %0, %1, %2;" : "=l"(o) : "l"(a), "l"(b));
  return o;
}

// monotone map: float bits -> u32 preserving float ordering (handles negatives)
__device__ __forceinline__ uint32_t f2ord(float f) {
  uint32_t u = __float_as_uint(f);
  return u ^ ((u & 0x80000000u) ? 0xFFFFFFFFu : 0x80000000u);
}

// ---------------------------------------------------------------------------
// Host-side PRNG derivation — PARTITIONABLE threefry semantics
// ---------------------------------------------------------------------------
static void compute_consts(FpsArgs* fa, PermArgs* pa) {
  for (int b = 0; b < BB; b++) {
    uint32_t fk0, fk1;
    threefry2x32(0u, 42u, 0u, (uint32_t)b, &fk0, &fk1);
    uint32_t k20, k21;
    threefry2x32(fk0, fk1, 0u, 1u, &k20, &k21);
    uint32_t s0, s1;
    threefry2x32(k20, k21, 0u, 0u, &s0, &s1);
    fa->start[b] = (int)((s0 ^ s1) & (NN - 1));
  }
  uint32_t rk0, rk1;
  threefry2x32(0u, 42u, 0u, 1u, &rk0, &rk1);
  for (int b = 0; b < BB; b++) {
    uint32_t k0, k1;
    threefry2x32(rk0, rk1, 0u, (uint32_t)b, &k0, &k1);
    for (int r = 0; r < 2; r++) {
      uint32_t n0, n1, c0, c1;
      threefry2x32(k0, k1, 0u, 0u, &n0, &n1);
      threefry2x32(k0, k1, 0u, 1u, &c0, &c1);
      pa->sub[b][r][0] = c0;
      pa->sub[b][r][1] = c1;
      k0 = n0; k1 = n1;
    }
  }
}

// ---------------------------------------------------------------------------
// Pre-pack kernel: g_pack[b][i] = (x, y, z, sn) with sn in reference op-order
// ---------------------------------------------------------------------------
__global__ __launch_bounds__(1024, 1)
void prepack_kernel(const float* __restrict__ pos) {
  const int b = blockIdx.x;
  const float* px = pos + (size_t)b * 3 * NN;
  const float* py = px + NN;
  const float* pz = px + 2 * NN;
  for (int i = threadIdx.x; i < NN; i += 1024) {
    float xx = px[i], yy = py[i], zz = pz[i];
    float sn = __fadd_rn(__fadd_rn(__fmul_rn(xx, xx), __fmul_rn(yy, yy)),
                         __fmul_rn(zz, zz));
    g_pack[b * NN + i] = make_float4(xx, yy, zz, sn);
  }
}

// Fused FPS + permutation kernel. Blocks 0..7 = FPS(batch), 8..15 = perm(batch)
#define SMEM_FUSED (3 * NN * 4 + 4 * 32 * 4 + 64)

__global__ __launch_bounds__(FT, 1)
void fused_kernel(const float* __restrict__ pos, FpsArgs fargs, PermArgs pargs) {
  extern __shared__ char smem_raw[];
  const int tid = threadIdx.x;

  if (blockIdx.x < BB) {
    const int b = blockIdx.x;
    float* sax = (float*)smem_raw;
    float* say = sax + NN;
    float* saz = say + NN;
    uint32_t* swval = (uint32_t*)(saz + NN);   // [2][8]
    uint32_t* swidx = swval + 32;              // [2][8]

    const float* px = pos + (size_t)b * 3 * NN;
    const float* py = px + NN;
    const float* pz = px + 2 * NN;

    unsigned long long rx2[16], ry2[16], rz2[16];
    float rd[32];
#pragma unroll
    for (int j = 0; j < 16; j++) {
      int i0 = (2 * j) * FT + tid;
      int i1 = i0 + FT;
      float x0 = px[i0], x1 = px[i1];
      float y0 = py[i0], y1 = py[i1];
      float z0 = pz[i0], z1 = pz[i1];
      rx2[j] = f2_pack(x0, x1);
      ry2[j] = f2_pack(y0, y1);
      rz2[j] = f2_pack(z0, z1);
      sax[i0] = x0; sax[i1] = x1;
      say[i0] = y0; say[i1] = y1;
      saz[i0] = z0; saz[i1] = z1;
      rd[2 * j] = 1e10f; rd[2 * j + 1] = 1e10f;
    }
    __syncthreads();

    const int start = fargs.start[b];
    if (tid == 0) g_idx[b * MM] = start;
    float bx = sax[start], by = say[start], bz = saz[start];

    const int lane = tid & 31, warp = tid >> 5;
    int par = 0;

    for (int it = 1; it < FPS_M; ++it) {
      unsigned long long nbx2 = f2_pack(-bx, -bx);
      unsigned long long nby2 = f2_pack(-by, -by);
      unsigned long long nbz2 = f2_pack(-bz, -bz);

      // value-only max tracking (2 FMNMX/pair); index resolved in epilogue
      float bestv = -1.0f;
#pragma unroll
      for (int j = 0; j < 16; j++) {
        unsigned long long dx2 = f2_add(rx2[j], nbx2);
        unsigned long long dy2 = f2_add(ry2[j], nby2);
        unsigned long long dz2 = f2_add(rz2[j], nbz2);
        unsigned long long dd2 =
            f2_add(f2_add(f2_mul(dx2, dx2), f2_mul(dy2, dy2)), f2_mul(dz2, dz2));
        float d0, d1;
        f2_unpack(dd2, &d0, &d1);
        float nv0 = fminf(rd[2 * j], d0);
        rd[2 * j] = nv0;
        float nv1 = fminf(rd[2 * j + 1], d1);
        rd[2 * j + 1] = nv1;
        bestv = fmaxf(bestv, fmaxf(nv0, nv1));
      }
      // epilogue: first (lowest global index) slot equal to bestv.
      // slot order (j asc, lo before hi) == ascending global index for a thread
      int besti = 0x7FFFFFFF;
#pragma unroll
      for (int j = 0; j < 32; j++) {
        int gi = j * FT + tid;  // j even = lo slots? No: slot j holds index j*FT+tid
        besti = (rd[j] == bestv) ? min(besti, gi) : besti;
      }
      uint32_t bits = __float_as_uint(bestv);
      uint32_t wmax = __reduce_max_sync(0xffffffffu, bits);
      uint32_t cand = (bits == wmax) ? (uint32_t)besti : 0xFFFFFFFFu;
      uint32_t wi   = __reduce_min_sync(0xffffffffu, cand);
      if (lane == 0) { swval[par * 8 + warp] = wmax; swidx[par * 8 + warp] = wi; }
      __syncthreads();
      uint32_t v    = (lane < 8) ? swval[par * 8 + lane] : 0u;
      uint32_t bmax = __reduce_max_sync(0xffffffffu, v);
      uint32_t bc   = (lane < 8 && v == bmax) ? swidx[par * 8 + lane] : 0xFFFFFFFFu;
      uint32_t w    = __reduce_min_sync(0xffffffffu, bc);
      if (tid == 0) g_idx[b * MM + it] = (int)w;
      bx = sax[w]; by = say[w]; bz = saz[w];
      par ^= 1;
    }
  } else {
    const int b = blockIdx.x - BB;
    unsigned long long* A = (unsigned long long*)smem_raw;

    for (int r = 0; r < 2; ++r) {
      const uint32_t k0 = pargs.sub[b][r][0];
      const uint32_t k1 = pargs.sub[b][r][1];
#pragma unroll 4
      for (int t = 0; t < 32; ++t) {
        int i = tid + t * FT;
        uint32_t y0, y1;
        threefry2x32(k0, k1, 0u, (uint32_t)i, &y0, &y1);
        uint32_t kk = y0 ^ y1;
        uint32_t v = (r == 0) ? (uint32_t)i : (uint32_t)(A[i] & 0x1FFFull);
        A[i] = ((unsigned long long)kk << 32) |
               ((unsigned long long)(uint32_t)i << 13) | v;
      }
      __syncthreads();
      for (int kk2 = 2; kk2 <= NN; kk2 <<= 1) {
        for (int jj = kk2 >> 1; jj > 0; jj >>= 1) {
#pragma unroll 4
          for (int t = 0; t < 32; ++t) {
            int i = tid + t * FT;
            int ixj = i ^ jj;
            if (ixj > i) {
              bool up = ((i & kk2) == 0);
              unsigned long long a = A[i], c = A[ixj];
              if ((a > c) == up) { A[i] = c; A[ixj] = a; }
            }
          }
          __syncthreads();
        }
      }
    }
    for (int t = tid; t < RAND_M; t += FT)
      g_idx[b * MM + FPS_M + t] = (int)(A[t] & 0x1FFFull);
  }
}

// ---------------------------------------------------------------------------
// merge16: exact 16-smallest of {cur (distributed), cand (distributed)}
// ---------------------------------------------------------------------------
__device__ __forceinline__ void merge16(unsigned long long& cur,
                                        unsigned long long cand,
                                        unsigned long long* top,
                                        float& tauf, int lane) {
#pragma unroll
  for (int r = 0; r < KNNK; ++r) {
    unsigned long long m = (cur < cand) ? cur : cand;
#pragma unroll
    for (int off = 16; off; off >>= 1) {
      unsigned long long o = __shfl_xor_sync(0xffffffffu, m, off);
      m = (o < m) ? o : m;
    }
    top[r] = m;
    if (cur == m) cur = INF64;
    else if (cand == m) cand = INF64;
  }
  cur = (lane < KNNK) ? top[lane] : INF64;
  unsigned long long t15 = top[15];
  if (t15 == INF64) {
    tauf = __int_as_float(0x7f800000);
  } else {
    uint32_t v = (uint32_t)(t15 >> 32);
    uint32_t bits = (v & 0x80000000u) ? (v ^ 0x80000000u) : ~v;
    tauf = __uint_as_float(bits);
  }
}

// ---------------------------------------------------------------------------
// KNN v4: warp-per-center + smem point tiles (8 warps share each tile load)
// ---------------------------------------------------------------------------
__global__ __launch_bounds__(256, 2)
void knn_kernel(const float* __restrict__ x, const float* __restrict__ pos,
                float* __restrict__ out) {
  __shared__ float4 spt[2048];                 // 32 KB point tile
  __shared__ unsigned long long sbuf[8][64];   // qualifier buffers
  const int warp = threadIdx.x >> 5, lane = threadIdx.x & 31;
  const int b  = blockIdx.x >> 8;
  const int ci = ((blockIdx.x & 255) << 3) + warp;
  const float* px = pos + (size_t)b * 3 * NN;
  const float4* pk = g_pack + (size_t)b * NN;

  const int cidx = g_idx[b * MM + ci];
  const float4 cc = pk[cidx];
  const float sx = cc.x, sy = cc.y, sz = cc.z, sm = cc.w;

  unsigned long long top[KNNK];
  unsigned long long cur = INF64;
  float tauf = __int_as_float(0x7f800000);  // +inf until seeded

  unsigned long long* buf = sbuf[warp];
  int base = 0;
  const uint32_t ltmask = (lane == 31) ? 0x7FFFFFFFu : ((1u << lane) - 1u);

  for (int tile = 0; tile < 4; ++tile) {
    __syncthreads();
    const int tbase = tile * 2048;
#pragma unroll
    for (int t = 0; t < 8; ++t)
      spt[threadIdx.x + t * 256] = pk[tbase + threadIdx.x + t * 256];
    __syncthreads();

    int s0 = 0;
    if (tile == 0) {
      // seed exact top-16 + threshold from the first 32 points
      float4 p = spt[lane];
      float dot = __fadd_rn(
          __fadd_rn(__fmul_rn(sx, p.x), __fmul_rn(sy, p.y)), __fmul_rn(sz, p.z));
      float d2 = __fsub_rn(__fadd_rn(sm, p.w), __fmul_rn(2.0f, dot));
      cur = ((unsigned long long)f2ord(d2) << 32) | (uint32_t)lane;
      merge16(cur, INF64, top, tauf, lane);
      s0 = 1;
    }
#pragma unroll 2
    for (int s = s0; s < 64; ++s) {
      const int li = (s << 5) | lane;
      float4 p = spt[li];
      float dot = __fadd_rn(
          __fadd_rn(__fmul_rn(sx, p.x), __fmul_rn(sy, p.y)), __fmul_rn(sz, p.z));
      float d2 = __fsub_rn(__fadd_rn(sm, p.w), __fmul_rn(2.0f, dot));
      bool pred = (d2 <= tauf);
      uint32_t mask = __ballot_sync(0xffffffffu, pred);
      if (mask) {
        int pre = __popc(mask & ltmask);
        if (pred)
          buf[base + pre] =
              ((unsigned long long)f2ord(d2) << 32) | (uint32_t)(tbase + li);
        base += __popc(mask);
        __syncwarp();
        while (base >= 32) {
          unsigned long long cand = buf[lane];
          merge16(cur, cand, top, tauf, lane);
          base -= 32;
          unsigned long long t = (lane < base) ? buf[32 + lane] : 0ull;
          __syncwarp();
          if (lane < base) buf[lane] = t;
          __syncwarp();
        }
      }
    }
  }
  if (base > 0) {
    __syncwarp();
    unsigned long long cand = (lane < base) ? buf[lane] : INF64;
    merge16(cur, cand, top, tauf, lane);
  }

  // softmax over exact euclidean distances (same ops as reference)
  int   id[KNNK];
  float w[KNNK];
  float maxl = -3.4e38f;
#pragma unroll
  for (int k = 0; k < KNNK; k++) {
    id[k] = (int)(top[k] & 0xFFFFFFFFull);
    float dx = px[id[k]] - sx, dy = px[NN + id[k]] - sy, dz = px[2 * NN + id[k]] - sz;
    float dn = sqrtf(dx * dx + dy * dy + dz * dz);
    dn = fmaxf(dn, 1e-6f);
    float l = -dn / 0.2f;
    w[k] = l;
    maxl = fmaxf(maxl, l);
  }
  float s = 0.0f;
#pragma unroll
  for (int k = 0; k < KNNK; k++) { w[k] = expf(w[k] - maxl); s += w[k]; }
  float inv = 1.0f / s;
#pragma unroll
  for (int k = 0; k < KNNK; k++) w[k] *= inv;

  if (lane == 0) {
    float* outpos = out + (size_t)BB * CC * MM;
    outpos[(size_t)b * 3 * MM + ci] = sx;
    outpos[(size_t)b * 3 * MM + MM + ci] = sy;
    outpos[(size_t)b * 3 * MM + 2 * MM + ci] = sz;
  }

  const float* xb = x + (size_t)b * CC * NN;
  const float* r0 = xb + (size_t)lane * NN;
  const float* r1 = xb + (size_t)(lane + 32) * NN;
  float acc0 = 0.0f, acc1 = 0.0f;
#pragma unroll
  for (int k = 0; k < KNNK; k++) {
    acc0 += w[k] * r0[id[k]];
    acc1 += w[k] * r1[id[k]];
  }
  out[((size_t)b * CC + lane) * MM + ci] = acc0;
  out[((size_t)b * CC + lane + 32) * MM + ci] = acc1;
}

// ---------------------------------------------------------------------------
extern "C" void kernel_launch(void* const* d_in, const int* in_sizes, int n_in,
                              void* d_out, int out_size) {
  const float* x   = (const float*)d_in[0];
  const float* pos = (const float*)d_in[1];
  (void)in_sizes; (void)n_in; (void)out_size;

  FpsArgs fa;
  PermArgs pa;
  compute_consts(&fa, &pa);

  cudaFuncSetAttribute(fused_kernel,
                       cudaFuncAttributeMaxDynamicSharedMemorySize, SMEM_FUSED);

  prepack_kernel<<<BB, 1024>>>(pos);
  fused_kernel<<<2 * BB, FT, SMEM_FUSED>>>(pos, fa, pa);
  knn_kernel<<<BB * 256, 256>>>(x, pos, (float*)d_out);
}